// round 7
// baseline (speedup 1.0000x reference)
#include <cuda_runtime.h>
#include <cuda_fp16.h>
#include <math.h>

#define TLEN 4161
#define TPAD 4224
#define NC 33
#define DM 768
#define HH 24
#define DIN 1536
#define CVD 1664
#define DPJ 3224

#define ALPHA (1.0f/1024.0f)   // activations x16, weights x64

static __device__ float g_x  [TLEN*DM];
static __device__ float g_x2 [TLEN*DM];
static __device__ float g_mam[TLEN*DM];
static __device__ float g_zx [(size_t)TLEN*DPJ];
static __device__ float g_xBC[(size_t)TPAD*CVD];
static __device__ float g_dt [TPAD*HH];
static __device__ float g_acs[NC*HH*128];
static __device__ float g_ct [NC*HH];
static __device__ float g_G  [NC*128*128];
static __device__ float g_st [NC*HH*4096];
static __device__ float g_se [NC*HH*4096];
static __device__ float g_y  [(size_t)TLEN*DIN];
static __device__ float g_img[4096*DM];
static __device__ float g_e8 [64*DM];
static __device__ float g_sq [12288];
static __device__ float g_part[(size_t)3*4096*768 + 130*768];
static __device__ __half g_pAh[(size_t)TLEN*DIN];
static __device__ __half g_pAl[(size_t)TLEN*DIN];
static __device__ __half g_pBh[(size_t)768*19200];
static __device__ __half g_pBl[(size_t)768*19200];

__device__ __forceinline__ float siluf(float x){ return x/(1.0f+expf(-x)); }

// ---------------- fp16-split helpers ----------------
__device__ __forceinline__ void splith(float x, __half& h, __half& l){
    h = __float2half_rn(x);
    l = __float2half_rn(x - __half2float(h));
}
__device__ __forceinline__ void mmah(float* d, const unsigned* a, const unsigned* b){
    asm volatile("mma.sync.aligned.m16n8k16.row.col.f32.f16.f16.f32 "
        "{%0,%1,%2,%3}, {%4,%5,%6,%7}, {%8,%9}, {%0,%1,%2,%3};\n"
        : "+f"(d[0]),"+f"(d[1]),"+f"(d[2]),"+f"(d[3])
        : "r"(a[0]),"r"(a[1]),"r"(a[2]),"r"(a[3]), "r"(b[0]),"r"(b[1]));
}
__device__ __forceinline__ void ldm_x4(unsigned* r, const __half* p){
    unsigned sa = (unsigned)__cvta_generic_to_shared(p);
    asm volatile("ldmatrix.sync.aligned.m8n8.x4.shared.b16 {%0,%1,%2,%3}, [%4];"
        : "=r"(r[0]),"=r"(r[1]),"=r"(r[2]),"=r"(r[3]) : "r"(sa));
}
__device__ __forceinline__ void cp16(void* s, const void* g){
    unsigned sa = (unsigned)__cvta_generic_to_shared(s);
    asm volatile("cp.async.cg.shared.global [%0], [%1], 16;\n" :: "r"(sa), "l"(g));
}
__device__ __forceinline__ void cp16z(void* s, const void* g, bool v){
    unsigned sa = (unsigned)__cvta_generic_to_shared(s);
    int sz = v ? 16 : 0;
    asm volatile("cp.async.cg.shared.global [%0], [%1], 16, %2;\n" :: "r"(sa), "l"(g), "r"(sz));
}
#define CP_COMMIT() asm volatile("cp.async.commit_group;\n")
#define CP_WAIT1()  asm volatile("cp.async.wait_group 1;\n")
#define CP_WAIT0()  asm volatile("cp.async.wait_group 0;\n")

// ---------- weight pack (no transpose): planes[n][K] = split(src * 64) ----------
__global__ void k_packw2(const float* __restrict__ src, __half* __restrict__ dh,
                         __half* __restrict__ dl, int n){
    int i = blockIdx.x*256 + threadIdx.x;
    if (i < n){
        __half h,l; splith(src[i]*64.0f, h, l);
        dh[i]=h; dl[i]=l;
    }
}

// ---------- conv weight transpose-pack: [19200,768] f32 -> planes [768][19200] ----------
__global__ void k_packwT(const float* __restrict__ src){
    __shared__ float tl[32][33];
    int k0 = blockIdx.x*32, n0 = blockIdx.y*32;
    int tx = threadIdx.x, ty = threadIdx.y;
    #pragma unroll
    for (int j=0;j<4;j++)
        tl[ty+8*j][tx] = src[(size_t)(k0+ty+8*j)*768 + n0 + tx];
    __syncthreads();
    #pragma unroll
    for (int j=0;j<4;j++){
        int n = n0 + ty + 8*j, k = k0 + tx;
        __half h,l; splith(tl[tx][ty+8*j]*64.0f, h, l);
        g_pBh[(size_t)n*19200 + k] = h;
        g_pBl[(size_t)n*19200 + k] = l;
    }
}

// ---------- build embeddings ----------
__global__ void k_e8(const float* __restrict__ im8, const float* __restrict__ w, const float* __restrict__ b){
    int i = blockIdx.x*256 + threadIdx.x;
    if (i >= 64*DM) return;
    int r = i/DM, d = i%DM;
    g_e8[i] = im8[r*3+0]*w[d*3+0] + im8[r*3+1]*w[d*3+1] + im8[r*3+2]*w[d*3+2] + b[d];
}
__global__ void k_buildx(const float* __restrict__ s0, const float* __restrict__ suffix){
    int i = blockIdx.x*256 + threadIdx.x;
    if (i >= TLEN*DM) return;
    int t = i/DM, d = i%DM;
    float v;
    if (t == 0) v = s0[d];
    else if (t <= 64) v = g_e8[(t-1)*DM + d];
    else {
        int p = t-65, py = p>>6, px = p&63;
        int blk = (py>>3)*8 + (px>>3);
        v = g_e8[blk*DM + d] + suffix[(size_t)p*DM + d];
    }
    g_x2[i] = v;
}

// ---------- layer norm -> fp32 out ----------
__global__ void k_ln(const float* __restrict__ in, float* __restrict__ out,
                     const float* __restrict__ w, const float* __restrict__ b){
    int t = blockIdx.x, tid = threadIdx.x;
    const float* x = in + (size_t)t*DM;
    float v0=x[tid], v1=x[tid+256], v2=x[tid+512];
    __shared__ float red[256];
    red[tid]=v0+v1+v2; __syncthreads();
    for (int o=128;o;o>>=1){ if(tid<o) red[tid]+=red[tid+o]; __syncthreads(); }
    float mu = red[0]*(1.0f/DM);
    __syncthreads();
    float d0=v0-mu, d1=v1-mu, d2=v2-mu;
    red[tid]=d0*d0+d1*d1+d2*d2; __syncthreads();
    for (int o=128;o;o>>=1){ if(tid<o) red[tid]+=red[tid+o]; __syncthreads(); }
    float r = rsqrtf(red[0]*(1.0f/DM) + 1e-5f);
    float* o = out + (size_t)t*DM;
    o[tid]=d0*r*w[tid]+b[tid]; o[tid+256]=d1*r*w[tid+256]+b[tid+256]; o[tid+512]=d2*r*w[tid+512]+b[tid+512];
}

// ---------- layer norm -> split planes (x16) ----------
__global__ void k_ln_pack2(const float* __restrict__ in,
                           __half* __restrict__ oh, __half* __restrict__ ol,
                           const float* __restrict__ w, const float* __restrict__ b){
    int t = blockIdx.x, tid = threadIdx.x;
    const float* x = in + (size_t)t*DM;
    float v0=x[tid], v1=x[tid+256], v2=x[tid+512];
    __shared__ float red[256];
    red[tid]=v0+v1+v2; __syncthreads();
    for (int o=128;o;o>>=1){ if(tid<o) red[tid]+=red[tid+o]; __syncthreads(); }
    float mu = red[0]*(1.0f/DM);
    __syncthreads();
    float d0=v0-mu, d1=v1-mu, d2=v2-mu;
    red[tid]=d0*d0+d1*d1+d2*d2; __syncthreads();
    for (int o=128;o;o>>=1){ if(tid<o) red[tid]+=red[tid+o]; __syncthreads(); }
    float r = rsqrtf(red[0]*(1.0f/DM) + 1e-5f);
    __half h,l;
    splith((d0*r*w[tid]+b[tid])*16.0f, h, l);         oh[(size_t)t*DM+tid]=h;     ol[(size_t)t*DM+tid]=l;
    splith((d1*r*w[tid+256]+b[tid+256])*16.0f, h, l); oh[(size_t)t*DM+tid+256]=h; ol[(size_t)t*DM+tid+256]=l;
    splith((d2*r*w[tid+512]+b[tid+512])*16.0f, h, l); oh[(size_t)t*DM+tid+512]=h; ol[(size_t)t*DM+tid+512]=l;
}

// ---------- SIMT NT sgemm (small batched G) ----------
__global__ void __launch_bounds__(256) k_gemm_nt(
    const float* __restrict__ A_, int lda, long long sA,
    const float* __restrict__ B_, int ldb, long long sB,
    float* __restrict__ C_, int ldc, long long sC,
    int M, int N, int K)
{
    const float* A = A_ + (size_t)blockIdx.z * sA;
    const float* B = B_ + (size_t)blockIdx.z * sB;
    float*       C = C_ + (size_t)blockIdx.z * sC;
    __shared__ float As[8][128];
    __shared__ float Bs[8][64];
    const int tid = threadIdx.x;
    const int m0 = blockIdx.y*128, n0 = blockIdx.x*64;
    const int alr = tid>>1, alc = (tid&1)*4;
    const int am = m0 + alr;
    const bool aok = am < M;
    const float* Ap = A + (size_t)(aok?am:0)*lda + alc;
    const int blr = tid>>1, blc = (tid&1)*4;
    const int bn = n0 + blr;
    const bool bld = tid < 128;
    const bool bok = bld && (bn < N);
    const float* Bp = B + (size_t)(bok?bn:0)*ldb + blc;
    const int row0 = (tid>>4)*8, col0 = (tid&15)*4;
    float acc[8][4];
    #pragma unroll
    for (int i=0;i<8;i++){
        #pragma unroll
        for (int j=0;j<4;j++) acc[i][j]=0.0f;
    }
    for (int k0=0;k0<K;k0+=8){
        float4 av = aok ? *(const float4*)(Ap+k0) : make_float4(0,0,0,0);
        float4 bv = bok ? *(const float4*)(Bp+k0) : make_float4(0,0,0,0);
        __syncthreads();
        As[alc+0][alr]=av.x; As[alc+1][alr]=av.y; As[alc+2][alr]=av.z; As[alc+3][alr]=av.w;
        if (bld){ Bs[blc+0][blr]=bv.x; Bs[blc+1][blr]=bv.y; Bs[blc+2][blr]=bv.z; Bs[blc+3][blr]=bv.w; }
        __syncthreads();
        #pragma unroll
        for (int kk=0;kk<8;kk++){
            float a[8], bb[4];
            *(float4*)&a[0] = *(const float4*)&As[kk][row0];
            *(float4*)&a[4] = *(const float4*)&As[kk][row0+4];
            *(float4*)&bb[0] = *(const float4*)&Bs[kk][col0];
            #pragma unroll
            for (int i=0;i<8;i++){
                #pragma unroll
                for (int j=0;j<4;j++) acc[i][j] = fmaf(a[i], bb[j], acc[i][j]);
            }
        }
    }
    #pragma unroll
    for (int i=0;i<8;i++){
        int m = m0+row0+i;
        if (m < M){
            #pragma unroll
            for (int j=0;j<4;j++){
                int n = n0+col0+j;
                if (n < N) C[(size_t)m*ldc + n] = acc[i][j];
            }
        }
    }
}

// ---------- fp16-split NT GEMM (separate planes, ldmatrix): C = ALPHA*A*B^T ----------
__global__ void __launch_bounds__(256,2) k_mma_nt2(
    const __half* __restrict__ Ah, const __half* __restrict__ Al, int lda,
    const __half* __restrict__ Bh, const __half* __restrict__ Bl, int ldb,
    float* __restrict__ C, int ldc, long long csplit,
    int M, int N, int K, int kchunk)
{
    __shared__ __align__(16) __half sAh[2][128][24];
    __shared__ __align__(16) __half sAl[2][128][24];
    __shared__ __align__(16) __half sBh[2][128][16];
    __shared__ __align__(16) __half sBl[2][128][16];
    const int tid = threadIdx.x;
    const int m0 = blockIdx.y*128, n0 = blockIdx.x*128;
    const int kbeg = blockIdx.z * kchunk;
    C += (long long)blockIdx.z * csplit;

    const int lr = tid>>1, lc = (tid&1)*8;
    const int am = min(m0+lr, M-1);
    const int bn = min(n0+lr, N-1);
    const __half* Ah_p = Ah + (size_t)am*lda + kbeg + lc;
    const __half* Al_p = Al + (size_t)am*lda + kbeg + lc;
    const __half* Bh_p = Bh + (size_t)bn*ldb + kbeg + lc;
    const __half* Bl_p = Bl + (size_t)bn*ldb + kbeg + lc;

    const int lane = tid&31, warp = tid>>5;
    const int wm = warp>>2, wn = warp&3;
    const int g = lane>>2, tg = lane&3;
    const int arow = wm*64 + (lane&7) + ((lane>>3)&1)*8;
    const int acol = ((lane>>4)&1)*8;
    const int brow = wn*32 + g;

    float acc[4][4][4];
    #pragma unroll
    for (int a=0;a<4;a++)
        #pragma unroll
        for (int b=0;b<4;b++)
            #pragma unroll
            for (int c=0;c<4;c++) acc[a][b][c]=0.0f;

    const int nst = kchunk/16;
    {
        cp16(&sAh[0][lr][lc], Ah_p);
        cp16(&sAl[0][lr][lc], Al_p);
        cp16(&sBh[0][lr][lc], Bh_p);
        cp16(&sBl[0][lr][lc], Bl_p);
        CP_COMMIT();
    }
    for (int s=0; s<nst; s++){
        const int buf = s&1;
        if (s+1 < nst){
            const int k0 = (s+1)*16;
            cp16(&sAh[buf^1][lr][lc], Ah_p + k0);
            cp16(&sAl[buf^1][lr][lc], Al_p + k0);
            cp16(&sBh[buf^1][lr][lc], Bh_p + k0);
            cp16(&sBl[buf^1][lr][lc], Bl_p + k0);
            CP_COMMIT();
            CP_WAIT1();
        } else {
            CP_WAIT0();
        }
        __syncthreads();
        unsigned af[4][4], bh[4][2], bl[4][2];
        #pragma unroll
        for (int nt=0; nt<4; nt++){
            bh[nt][0] = *(const unsigned*)&sBh[buf][brow+nt*8][2*tg];
            bh[nt][1] = *(const unsigned*)&sBh[buf][brow+nt*8][2*tg+8];
            bl[nt][0] = *(const unsigned*)&sBl[buf][brow+nt*8][2*tg];
            bl[nt][1] = *(const unsigned*)&sBl[buf][brow+nt*8][2*tg+8];
        }
        #pragma unroll
        for (int mt=0; mt<4; mt++) ldm_x4(af[mt], &sAh[buf][arow+mt*16][acol]);
        #pragma unroll
        for (int mt=0; mt<4; mt++)
            #pragma unroll
            for (int nt=0; nt<4; nt++){
                mmah(&acc[mt][nt][0], af[mt], bh[nt]);
                mmah(&acc[mt][nt][0], af[mt], bl[nt]);
            }
        #pragma unroll
        for (int mt=0; mt<4; mt++) ldm_x4(af[mt], &sAl[buf][arow+mt*16][acol]);
        #pragma unroll
        for (int mt=0; mt<4; mt++)
            #pragma unroll
            for (int nt=0; nt<4; nt++)
                mmah(&acc[mt][nt][0], af[mt], bh[nt]);
        __syncthreads();
    }

    #pragma unroll
    for (int mt=0; mt<4; mt++){
        #pragma unroll
        for (int nt=0; nt<4; nt++){
            int m = m0 + wm*64 + mt*16 + g;
            int n = n0 + wn*32 + nt*8 + 2*tg;
            if (n < N){
                if (m < M){
                    float2 v; v.x = acc[mt][nt][0]*ALPHA; v.y = acc[mt][nt][1]*ALPHA;
                    *(float2*)&C[(size_t)m*ldc + n] = v;
                }
                if (m+8 < M){
                    float2 v; v.x = acc[mt][nt][2]*ALPHA; v.y = acc[mt][nt][3]*ALPHA;
                    *(float2*)&C[(size_t)(m+8)*ldc + n] = v;
                }
            }
        }
    }
}

// ---------- fp16-split implicit-GEMM conv2d (planes + transposed weights, split-K=3) ----------
__global__ void __launch_bounds__(256,2) k_conv2d_mma2(){
    __shared__ __align__(16) __half sAh[2][128][24];
    __shared__ __align__(16) __half sAl[2][128][24];
    __shared__ __align__(16) __half sBh[2][128][16];
    __shared__ __align__(16) __half sBl[2][128][16];
    const int tid = threadIdx.x;
    const int n0 = blockIdx.x*128;
    const int m0 = blockIdx.y*128;
    const int z  = blockIdx.z;
    const int sbeg = z*400;

    const int lr = tid>>1, lc = (tid&1)*8;
    const int m = m0 + lr;
    const int py = m>>6, px = m&63;
    const __half* Bh_p = g_pBh + (size_t)(n0+lr)*19200 + lc;
    const __half* Bl_p = g_pBl + (size_t)(n0+lr)*19200 + lc;

    const int lane = tid&31, warp = tid>>5;
    const int wm = warp>>2, wn = warp&3;
    const int g = lane>>2, tg = lane&3;
    const int arow = wm*64 + (lane&7) + ((lane>>3)&1)*8;
    const int acol = ((lane>>4)&1)*8;
    const int brow = wn*32 + g;

    float acc[4][4][4];
    #pragma unroll
    for (int a=0;a<4;a++)
        #pragma unroll
        for (int b=0;b<4;b++)
            #pragma unroll
            for (int c=0;c<4;c++) acc[a][b][c]=0.0f;

    {
        const int k0 = sbeg*16;
        const int tap = k0/768, ci = k0 - tap*768;
        const int ky = tap/5 - 2, kx = tap - (tap/5)*5 - 2;
        int sy=py+ky, sx=px+kx; bool v = ((unsigned)sy<64u) && ((unsigned)sx<64u);
        int o = v ? ((sy<<6)+sx) : 0;
        cp16z(&sAh[0][lr][lc], &g_pAh[(size_t)o*768 + ci + lc], v);
        cp16z(&sAl[0][lr][lc], &g_pAl[(size_t)o*768 + ci + lc], v);
        cp16(&sBh[0][lr][lc], Bh_p + k0);
        cp16(&sBl[0][lr][lc], Bl_p + k0);
        CP_COMMIT();
    }
    for (int s=0; s<400; s++){
        const int buf = s&1;
        if (s+1 < 400){
            const int k0 = (sbeg+s+1)*16;
            const int tap = k0/768, ci = k0 - tap*768;
            const int ky = tap/5 - 2, kx = tap - (tap/5)*5 - 2;
            int sy=py+ky, sx=px+kx; bool v = ((unsigned)sy<64u) && ((unsigned)sx<64u);
            int o = v ? ((sy<<6)+sx) : 0;
            cp16z(&sAh[buf^1][lr][lc], &g_pAh[(size_t)o*768 + ci + lc], v);
            cp16z(&sAl[buf^1][lr][lc], &g_pAl[(size_t)o*768 + ci + lc], v);
            cp16(&sBh[buf^1][lr][lc], Bh_p + k0);
            cp16(&sBl[buf^1][lr][lc], Bl_p + k0);
            CP_COMMIT();
            CP_WAIT1();
        } else {
            CP_WAIT0();
        }
        __syncthreads();
        unsigned af[4][4], bh[4][2], bl[4][2];
        #pragma unroll
        for (int nt=0; nt<4; nt++){
            bh[nt][0] = *(const unsigned*)&sBh[buf][brow+nt*8][2*tg];
            bh[nt][1] = *(const unsigned*)&sBh[buf][brow+nt*8][2*tg+8];
            bl[nt][0] = *(const unsigned*)&sBl[buf][brow+nt*8][2*tg];
            bl[nt][1] = *(const unsigned*)&sBl[buf][brow+nt*8][2*tg+8];
        }
        #pragma unroll
        for (int mt=0; mt<4; mt++) ldm_x4(af[mt], &sAh[buf][arow+mt*16][acol]);
        #pragma unroll
        for (int mt=0; mt<4; mt++)
            #pragma unroll
            for (int nt=0; nt<4; nt++){
                mmah(&acc[mt][nt][0], af[mt], bh[nt]);
                mmah(&acc[mt][nt][0], af[mt], bl[nt]);
            }
        #pragma unroll
        for (int mt=0; mt<4; mt++) ldm_x4(af[mt], &sAl[buf][arow+mt*16][acol]);
        #pragma unroll
        for (int mt=0; mt<4; mt++)
            #pragma unroll
            for (int nt=0; nt<4; nt++)
                mmah(&acc[mt][nt][0], af[mt], bh[nt]);
        __syncthreads();
    }

    float* P = g_part + (size_t)z*4096*768;
    #pragma unroll
    for (int mt=0; mt<4; mt++){
        #pragma unroll
        for (int nt=0; nt<4; nt++){
            int mm = m0 + wm*64 + mt*16 + g;
            int nn = n0 + wn*32 + nt*8 + 2*tg;
            float2 v0; v0.x = acc[mt][nt][0]*ALPHA; v0.y = acc[mt][nt][1]*ALPHA;
            *(float2*)&P[(size_t)mm*768 + nn] = v0;
            float2 v1; v1.x = acc[mt][nt][2]*ALPHA; v1.y = acc[mt][nt][3]*ALPHA;
            *(float2*)&P[(size_t)(mm+8)*768 + nn] = v1;
        }
    }
}

// ---------- split-K reductions ----------
__global__ void k_red2(){
    int i = blockIdx.x*256 + threadIdx.x;
    if (i >= TLEN*DM) return;
    const size_t S = (size_t)TLEN*DM;
    g_mam[i] = g_part[i] + g_part[i+S];
}
__global__ void k_red3b(const float* __restrict__ bias){
    int i = blockIdx.x*256 + threadIdx.x;
    if (i >= 4096*768) return;
    const size_t S = (size_t)4096*768;
    g_img[i] = g_part[i] + g_part[i+S] + g_part[i+2*S] + bias[i%768];
}

// ---------- dt = softplus(raw + bias) ----------
__global__ void k_dt(const float* __restrict__ dtb){
    int i = blockIdx.x*256 + threadIdx.x;
    if (i >= TPAD*HH) return;
    int t = i/HH, h = i%HH;
    float v = 0.0f;
    if (t < TLEN){
        float x = g_zx[(size_t)t*DPJ + 3200 + h] + dtb[h];
        v = (x > 20.0f) ? x : log1pf(expf(x));
    }
    g_dt[i] = v;
}

// ---------- causal depthwise conv1d (k=4) + silu ----------
__global__ void k_conv1d(const float* __restrict__ cw, const float* __restrict__ cb){
    int c = blockIdx.x*256 + threadIdx.x;
    if (c >= CVD) return;
    int t = blockIdx.y;
    float v = 0.0f;
    if (t < TLEN){
        float s = cb[c];
        #pragma unroll
        for (int j=0;j<4;j++){
            int ts = t-3+j;
            if (ts >= 0) s += cw[c*4+j]*g_zx[(size_t)ts*DPJ + 1536 + c];
        }
        v = siluf(s);
    }
    g_xBC[(size_t)t*CVD + c] = v;
}

// ---------- per-(chunk,head) cumsum of a = dt * (-exp(A_log)) ----------
__global__ void k_chunkscan(const float* __restrict__ A_log){
    int bb = blockIdx.x, c = bb/HH, h = bb%HH, tid = threadIdx.x;
    float Ah = -expf(A_log[h]);
    float a = g_dt[(c*128+tid)*HH + h] * Ah;
    __shared__ float sh[128];
    sh[tid] = a; __syncthreads();
    for (int o=1;o<128;o<<=1){
        float v = (tid>=o) ? sh[tid-o] : 0.0f;
        __syncthreads();
        sh[tid] += v;
        __syncthreads();
    }
    g_acs[bb*128+tid] = sh[tid];
    if (tid == 127) g_ct[bb] = sh[tid];
}

// ---------- chunk states ----------
__global__ void __launch_bounds__(256) k_states(){
    int h = blockIdx.x, c = blockIdx.y, ch = c*HH+h, tid = threadIdx.x;
    __shared__ float Bw[64][64];
    __shared__ float Xs[64][64];
    __shared__ float wl[64], dl[64];
    float ctot = g_ct[ch];
    int n0 = (tid>>4)*4, p0 = (tid&15)*4;
    float acc[4][4];
    #pragma unroll
    for (int i=0;i<4;i++){
        #pragma unroll
        for (int j=0;j<4;j++) acc[i][j]=0.0f;
    }
    for (int l0=0;l0<128;l0+=64){
        __syncthreads();
        if (tid < 64){
            int t = c*128 + l0 + tid;
            wl[tid] = expf(ctot - g_acs[ch*128 + l0 + tid]);
            dl[tid] = g_dt[t*HH + h];
        }
        __syncthreads();
        for (int i=tid;i<64*64;i+=256){
            int l = i>>6, q = i&63;
            const float* row = &g_xBC[(size_t)(c*128+l0+l)*CVD];
            Bw[l][q] = row[1536+q]*wl[l];
            Xs[l][q] = row[h*64+q]*dl[l];
        }
        __syncthreads();
        for (int l=0;l<64;l++){
            float a[4], bb[4];
            *(float4*)&a[0]  = *(const float4*)&Bw[l][n0];
            *(float4*)&bb[0] = *(const float4*)&Xs[l][p0];
            #pragma unroll
            for (int i=0;i<4;i++){
                #pragma unroll
                for (int j=0;j<4;j++) acc[i][j] = fmaf(a[i], bb[j], acc[i][j]);
            }
        }
    }
    float* o = &g_st[(size_t)ch*4096];
    #pragma unroll
    for (int i=0;i<4;i++){
        #pragma unroll
        for (int j=0;j<4;j++) o[(n0+i)*64 + p0+j] = acc[i][j];
    }
}

// ---------- inter-chunk serial recurrence ----------
__global__ void k_state_scan(){
    int h = blockIdx.x, tid = threadIdx.x;
    float S[16];
    #pragma unroll
    for (int j=0;j<16;j++) S[j]=0.0f;
    for (int z=0;z<NC;z++){
        int ch = z*HH + h;
        float f = expf(g_ct[ch]);
        float* se = &g_se[(size_t)ch*4096];
        const float* st = &g_st[(size_t)ch*4096];
        #pragma unroll
        for (int j=0;j<16;j++){
            int idx = tid + j*256;
            se[idx] = S[j];
            S[j] = f*S[j] + st[idx];
        }
    }
}

// ---------- Y = Yd + Yo + D*xh per (chunk,head) ----------
__global__ void __launch_bounds__(256) k_y(const float* __restrict__ A_log, const float* __restrict__ Dp){
    int h = blockIdx.x, c = blockIdx.y, ch = c*HH+h, tid = threadIdx.x;
    __shared__ float sA[128][33];
    __shared__ float sB[32][68];
    __shared__ float sAcs[128];
    __shared__ float sEap[128];
    int p0 = (tid&15)*4, l0 = (tid>>4)*8;
    if (tid < 128){
        sAcs[tid] = g_acs[ch*128+tid];
        float Ah = -expf(A_log[h]);
        sEap[tid] = expf(g_dt[(c*128+tid)*HH + h]*Ah);
    }
    __syncthreads();
    float acc[8][4];
    #pragma unroll
    for (int i=0;i<8;i++){
        #pragma unroll
        for (int j=0;j<4;j++) acc[i][j]=0.0f;
    }
    for (int n0=0;n0<64;n0+=32){
        __syncthreads();
        for (int i=tid;i<128*32;i+=256){
            int l=i>>5, nc=i&31;
            sA[l][nc] = g_xBC[(size_t)(c*128+l)*CVD + 1600 + n0 + nc];
        }
        for (int i=tid;i<32*64;i+=256){
            int nc=i>>6, p=i&63;
            sB[nc][p] = g_se[(size_t)ch*4096 + (n0+nc)*64 + p];
        }
        __syncthreads();
        for (int nc=0;nc<32;nc++){
            float bb[4];
            *(float4*)&bb[0] = *(const float4*)&sB[nc][p0];
            #pragma unroll
            for (int i=0;i<8;i++){
                float a = sA[l0+i][nc];
                #pragma unroll
                for (int j=0;j<4;j++) acc[i][j] = fmaf(a, bb[j], acc[i][j]);
            }
        }
    }
    #pragma unroll
    for (int i=0;i<8;i++){
        float e = expf(sAcs[l0+i]);
        #pragma unroll
        for (int j=0;j<4;j++) acc[i][j] *= e;
    }
    float m[8];
    #pragma unroll
    for (int i=0;i<8;i++) m[i]=0.0f;
    for (int s0=96;s0>=0;s0-=32){
        __syncthreads();
        for (int i=tid;i<128*32;i+=256){
            int l=i>>5, sc=i&31;
            sA[l][sc] = g_G[(size_t)c*16384 + l*128 + s0 + sc];
        }
        for (int i=tid;i<32*64;i+=256){
            int sc=i>>6, p=i&63;
            int t = c*128 + s0 + sc;
            sB[sc][p] = g_xBC[(size_t)t*CVD + h*64 + p]*g_dt[t*HH + h];
        }
        __syncthreads();
        if (l0+7 >= s0){
            for (int sc=31;sc>=0;sc--){
                int s = s0+sc;
                float es = sEap[(s+1)&127];
                float bb[4];
                *(float4*)&bb[0] = *(const float4*)&sB[sc][p0];
                #pragma unroll
                for (int i=0;i<8;i++){
                    int l = l0+i;
                    m[i] = (l==s) ? 1.0f : m[i]*es;
                    float co = (l>=s) ? sA[l][sc]*m[i] : 0.0f;
                    #pragma unroll
                    for (int j=0;j<4;j++) acc[i][j] = fmaf(co, bb[j], acc[i][j]);
                }
            }
        }
    }
    float Dph = Dp[h];
    #pragma unroll
    for (int i=0;i<8;i++){
        int t = c*128 + l0 + i;
        if (t < TLEN){
            #pragma unroll
            for (int j=0;j<4;j++){
                float xh = g_xBC[(size_t)t*CVD + h*64 + p0 + j];
                g_y[(size_t)t*DIN + h*64 + p0 + j] = acc[i][j] + Dph*xh;
            }
        }
    }
}

// ---------- y = y*silu(z); rmsnorm * rms_w; split planes (x16) ----------
__global__ void k_gaterms2(const float* __restrict__ rmsw,
                           __half* __restrict__ oh, __half* __restrict__ ol){
    int t = blockIdx.x, tid = threadIdx.x;
    const float* z = &g_zx[(size_t)t*DPJ];
    const float* y = &g_y[(size_t)t*DIN];
    float v[6]; float ss=0.0f;
    #pragma unroll
    for (int j=0;j<6;j++){
        int k = tid + j*256;
        float g = z[k];
        float val = y[k]*siluf(g);
        v[j]=val; ss += val*val;
    }
    __shared__ float red[256];
    red[tid]=ss; __syncthreads();
    for (int o=128;o;o>>=1){ if(tid<o) red[tid]+=red[tid+o]; __syncthreads(); }
    float r = rsqrtf(red[0]*(1.0f/DIN) + 1e-5f);
    #pragma unroll
    for (int j=0;j<6;j++){
        int k = tid + j*256;
        __half h,l; splith(v[j]*r*rmsw[k]*16.0f, h, l);
        oh[(size_t)t*DIN+k]=h; ol[(size_t)t*DIN+k]=l;
    }
}

// ---------- residual + image flip ----------
__global__ void k_resid(const float* __restrict__ cur, float* __restrict__ nxt){
    int i = blockIdx.x*256 + threadIdx.x;
    if (i >= TLEN*DM) return;
    int t = i/DM, d = i%DM;
    float hv; int td;
    if (t < 65){ hv = g_mam[i]; td = t; }
    else { int p = t-65; hv = g_img[(size_t)p*DM + d]; td = 65 + (4095-p); }
    nxt[(size_t)td*DM + d] = cur[i] + hv;
}

// ---------- final projection + squared errors ----------
__global__ void k_yhat(const float* __restrict__ x, const float* __restrict__ w,
                       const float* __restrict__ b, const float* __restrict__ im64,
                       float* __restrict__ out, int out_size){
    int p = blockIdx.x;
    int ch = threadIdx.x>>5, lane = threadIdx.x&31;
    const float* xr = x + (size_t)(65+p)*DM;
    float s = 0.0f;
    for (int k=lane;k<DM;k+=32) s += xr[k]*w[ch*DM+k];
    for (int o=16;o;o>>=1) s += __shfl_down_sync(0xffffffffu, s, o);
    if (lane == 0){
        float yh = s + b[ch];
        int idx = p*3 + ch;
        int cap = out_size - (out_size&1);
        if (idx < cap) out[idx] = yh;
        float d = yh - im64[idx];
        g_sq[idx] = d*d;
    }
}
__global__ void k_loss(float* __restrict__ out, int out_size){
    int tid = threadIdx.x;
    float s = 0.0f;
    for (int i=tid;i<12288;i+=256) s += g_sq[i];
    __shared__ float red[256];
    red[tid]=s; __syncthreads();
    for (int o=128;o;o>>=1){ if(tid<o) red[tid]+=red[tid+o]; __syncthreads(); }
    if (tid==0 && (out_size&1)) out[out_size-1] = red[0]*(1.0f/12288.0f);
}

extern "C" void kernel_launch(void* const* d_in, const int* in_sizes, int n_in,
                              void* d_out, int out_size){
    const float* im8       = (const float*)d_in[0];
    const float* im64      = (const float*)d_in[1];
    const float* from_rgbw = (const float*)d_in[2];
    const float* from_rgbb = (const float*)d_in[3];
    const float* to_rgbw   = (const float*)d_in[4];
    const float* to_rgbb   = (const float*)d_in[5];
    const float* s0        = (const float*)d_in[6];
    const float* suffix    = (const float*)d_in[7];
    const float* norm0w    = (const float*)d_in[8];
    const float* norm0b    = (const float*)d_in[9];
    const float* in_projw  = (const float*)d_in[10];
    const float* conv1dw   = (const float*)d_in[11];
    const float* conv1db   = (const float*)d_in[12];
    const float* dt_bias   = (const float*)d_in[13];
    const float* A_log     = (const float*)d_in[14];
    const float* Dp        = (const float*)d_in[15];
    const float* rms_w     = (const float*)d_in[16];
    const float* out_projw = (const float*)d_in[17];
    const float* ln_w      = (const float*)d_in[18];
    const float* ln_b      = (const float*)d_in[19];
    const float* lnc_w     = (const float*)d_in[20];
    const float* lnc_b     = (const float*)d_in[21];
    const float* conv2dw   = (const float*)d_in[22];
    const float* conv2db   = (const float*)d_in[23];

    float *px, *px2, *pmam, *pzx, *pxbc, *pG, *ppart;
    __half *pAh, *pAl, *pBh, *pBl;
    cudaGetSymbolAddress((void**)&px,   g_x);
    cudaGetSymbolAddress((void**)&px2,  g_x2);
    cudaGetSymbolAddress((void**)&pmam, g_mam);
    cudaGetSymbolAddress((void**)&pzx,  g_zx);
    cudaGetSymbolAddress((void**)&pxbc, g_xBC);
    cudaGetSymbolAddress((void**)&pG,   g_G);
    cudaGetSymbolAddress((void**)&ppart,g_part);
    cudaGetSymbolAddress((void**)&pAh,  g_pAh);
    cudaGetSymbolAddress((void**)&pAl,  g_pAl);
    cudaGetSymbolAddress((void**)&pBh,  g_pBh);
    cudaGetSymbolAddress((void**)&pBl,  g_pBl);

    const int NB = (TLEN*DM + 255)/256;

    k_e8<<<(64*DM+255)/256, 256>>>(im8, from_rgbw, from_rgbb);
    k_buildx<<<NB, 256>>>(s0, suffix);
    k_ln<<<TLEN, 256>>>(px2, px, norm0w, norm0b);

    float* cur = px; float* nxt = px2;
    for (int i=0;i<8;i++){
        k_ln_pack2<<<TLEN, 256>>>(cur, pAh, pAl, ln_w + i*DM, ln_b + i*DM);
        k_packw2<<<(DPJ*DM+255)/256, 256>>>(in_projw + (size_t)i*DPJ*DM, pBh, pBl, DPJ*DM);
        k_mma_nt2<<<dim3(26,33,1), 256>>>(pAh, pAl, DM, pBh, pBl, DM,
                                          pzx, DPJ, 0LL, TLEN, DPJ, DM, DM);
        k_dt<<<(TPAD*HH+255)/256, 256>>>(dt_bias + i*HH);
        k_conv1d<<<dim3(7, TPAD), 256>>>(conv1dw + (size_t)i*CVD*4, conv1db + i*CVD);
        k_chunkscan<<<NC*HH, 128>>>(A_log + i*HH);
        k_gemm_nt<<<dim3(2,1,NC), 256>>>(pxbc + 1600, CVD, (long long)128*CVD,
                                         pxbc + 1536, CVD, (long long)128*CVD,
                                         pG, 128, 16384, 128, 128, 64);
        k_states<<<dim3(HH,NC), 256>>>();
        k_state_scan<<<HH, 256>>>();
        k_y<<<dim3(HH,NC), 256>>>(A_log + i*HH, Dp + i*HH);
        k_gaterms2<<<TLEN, 256>>>(rms_w + (size_t)i*DIN, pAh, pAl);
        k_packw2<<<(DM*DIN+255)/256, 256>>>(out_projw + (size_t)i*DM*DIN, pBh, pBl, DM*DIN);
        k_mma_nt2<<<dim3(6,33,2), 256>>>(pAh, pAl, DIN, pBh, pBl, DIN,
                                         ppart, DM, (long long)TLEN*DM, TLEN, DM, DIN, 768);
        k_red2<<<NB, 256>>>();
        k_ln_pack2<<<4096, 256>>>(pmam + (size_t)65*DM, pAh, pAl, lnc_w + i*DM, lnc_b + i*DM);
        k_packwT<<<dim3(600,24), dim3(32,8)>>>(conv2dw + (size_t)i*14745600);
        k_conv2d_mma2<<<dim3(6,32,3), 256>>>();
        k_red3b<<<(4096*768+255)/256, 256>>>(conv2db + i*DM);
        k_resid<<<NB, 256>>>(cur, nxt);
        float* tmp = cur; cur = nxt; nxt = tmp;
    }
    k_yhat<<<4096, 96>>>(cur, to_rgbw, to_rgbb, im64, (float*)d_out, out_size);
    k_loss<<<1, 256>>>((float*)d_out, out_size);
}